// round 5
// baseline (speedup 1.0000x reference)
#include <cuda_runtime.h>
#include <cuda_bf16.h>
#include <cstdint>

#define BB 2
#define NTOK 256
#define DD 512
#define HH 2048
#define MM (BB*NTOK)   /* 512 rows total */

typedef unsigned long long ull;

// ---------------- scratch (device globals: allocation-free) ----------------
__device__ __nv_bfloat16 g_xwhi[2*MM*DD],  g_xwlo[2*MM*DD];     // [side][m][k]
__device__ __nv_bfloat16 g_w1thi[2*HH*DD], g_w1tlo[2*HH*DD];    // [side][n=2048][k=512]
__device__ __nv_bfloat16 g_wmthi[2*DD*HH], g_wmtlo[2*DD*HH];    // [side][n=512][k=2048]
__device__ __nv_bfloat16 g_wothi[DD*2*DD], g_wotlo[DD*2*DD];    // [n=512][k=1024]
__device__ __nv_bfloat16 g_h1hi[2*MM*HH],  g_h1lo[2*MM*HH];     // [side][m][k=2048]
__device__ float         g_p2[8*MM*DD];                         // [side*4+sp][m][n]
__device__ __nv_bfloat16 g_combhi[MM*2*DD], g_comblo[MM*2*DD];  // [m][k=1024]
__device__ float         g_p3[8*MM*DD];                         // [sp][m][n]

// ---------------- helpers ----------------
__device__ __forceinline__ uint32_t smem_u32(const void* p){
    uint32_t a;
    asm("{ .reg .u64 t; cvta.to.shared.u64 t, %1; cvt.u32.u64 %0, t; }" : "=r"(a) : "l"(p));
    return a;
}
__device__ __forceinline__ ull addx2(ull a, ull b){
    ull d; asm("add.rn.f32x2 %0, %1, %2;" : "=l"(d) : "l"(a), "l"(b)); return d;
}
__device__ __forceinline__ float2 unpk2(ull v){
    uint32_t lo, hi;
    asm("mov.b64 {%0, %1}, %2;" : "=r"(lo), "=r"(hi) : "l"(v));
    return make_float2(__uint_as_float(lo), __uint_as_float(hi));
}
__device__ __forceinline__ void split_bf16(float v, __nv_bfloat16& h, __nv_bfloat16& l){
    h = __float2bfloat16(v);
    l = __float2bfloat16(v - __bfloat162float(h));
}
__device__ __forceinline__ float gelu1(float x){
    return 0.5f*x*(1.0f + erff(x*0.70710678118654752f));
}

// ---------------- cp.async / ldmatrix / mma (baseline sm_80+ PTX) ----------
__device__ __forceinline__ void cp16(uint32_t s, const void* g){
    asm volatile("cp.async.ca.shared.global [%0], [%1], 16;" :: "r"(s), "l"(g) : "memory");
}
#define CP_COMMIT() asm volatile("cp.async.commit_group;" ::: "memory")
#define CP_WAIT2()  asm volatile("cp.async.wait_group 2;" ::: "memory")
#define CP_WAIT1()  asm volatile("cp.async.wait_group 1;" ::: "memory")
#define CP_WAIT0()  asm volatile("cp.async.wait_group 0;" ::: "memory")

#define LDM4(r, addr) \
    asm volatile("ldmatrix.sync.aligned.m8n8.x4.shared.b16 {%0,%1,%2,%3}, [%4];" \
        : "=r"((r)[0]), "=r"((r)[1]), "=r"((r)[2]), "=r"((r)[3]) : "r"(addr))
#define LDM2(r, addr) \
    asm volatile("ldmatrix.sync.aligned.m8n8.x2.shared.b16 {%0,%1}, [%2];" \
        : "=r"((r)[0]), "=r"((r)[1]) : "r"(addr))

#define MMA_BF16(d, a, b) \
    asm volatile("mma.sync.aligned.m16n8k16.row.col.f32.bf16.bf16.f32 " \
        "{%0,%1,%2,%3}, {%4,%5,%6,%7}, {%8,%9}, {%0,%1,%2,%3};" \
        : "+f"((d)[0]), "+f"((d)[1]), "+f"((d)[2]), "+f"((d)[3]) \
        : "r"((a)[0]), "r"((a)[1]), "r"((a)[2]), "r"((a)[3]), \
          "r"((b)[0]), "r"((b)[1]))

// CTA tile 128(M) x 64(N), BK=32. Rows: 32 bf16 payload (64B) padded to 80B
// (stride 20 banks -> ldmatrix conflict-free). 3 stages, 2 CTAs/SM.
#define ROWB    80
#define TILE_A  (128*ROWB)                /* 10240 */
#define TILE_Bb (64*ROWB)                 /*  5120 */
#define OFF_AL  TILE_A                    /* 10240 */
#define OFF_BH  (2*TILE_A)                /* 20480 */
#define OFF_BL  (2*TILE_A + TILE_Bb)      /* 25600 */
#define STAGE_B (2*TILE_A + 2*TILE_Bb)    /* 30720 */
#define NSTAGE  3
#define SMEM_BYTES (NSTAGE*STAGE_B)       /* 92160 */

// ---------------------------------------------------------------------------
// issue cp.async for one BK=32 stage (128 threads)
// A: thread t -> row t (64B). B: row t>>1, 32B half t&1.
// ---------------------------------------------------------------------------
__device__ __forceinline__ void issue_stage(
    uint32_t sb,
    const __nv_bfloat16* __restrict__ Ah, const __nv_bfloat16* __restrict__ Al, int lda,
    const __nv_bfloat16* __restrict__ Bh, const __nv_bfloat16* __restrict__ Bl, int ldb,
    int k0, int t)
{
    const uint32_t soa = (uint32_t)(t*ROWB);
    const size_t   ga  = (size_t)t*lda + k0;
    cp16(sb + soa,          Ah + ga);      cp16(sb + soa + 16,          Ah + ga + 8);
    cp16(sb + soa + 32,     Ah + ga + 16); cp16(sb + soa + 48,          Ah + ga + 24);
    cp16(sb + OFF_AL + soa,          Al + ga);      cp16(sb + OFF_AL + soa + 16, Al + ga + 8);
    cp16(sb + OFF_AL + soa + 32,     Al + ga + 16); cp16(sb + OFF_AL + soa + 48, Al + ga + 24);

    const int brow = t >> 1, bhalf = t & 1;
    const uint32_t sob = (uint32_t)(brow*ROWB + bhalf*32);
    const size_t   gb  = (size_t)brow*ldb + k0 + bhalf*16;
    cp16(sb + OFF_BH + sob, Bh + gb); cp16(sb + OFF_BH + sob + 16, Bh + gb + 8);
    cp16(sb + OFF_BL + sob, Bl + gb); cp16(sb + OFF_BL + sob + 16, Bl + gb + 8);
}

// ---------------------------------------------------------------------------
// compute one BK=32 stage: warp grid 2(m) x 2(n), warp tile 64x32.
// ---------------------------------------------------------------------------
__device__ __forceinline__ void compute_stage(
    uint32_t sb, int warp_m, int warp_n, int lane, float acc[4][4][4])
{
    const int arow = lane & 15;
    const int acol = (lane >> 4) * 8;
    const int brow = lane & 7;
    const int bcol = ((lane >> 3) & 1) * 8;

    #pragma unroll
    for (int kk = 0; kk < 32; kk += 16){
        uint32_t ah[4][4], al[4][4], bh[4][2], bl[4][2];
        #pragma unroll
        for (int mt = 0; mt < 4; ++mt){
            const uint32_t ao = (uint32_t)((warp_m*64 + mt*16 + arow)*ROWB + (kk + acol)*2);
            LDM4(ah[mt], sb + ao);
            LDM4(al[mt], sb + OFF_AL + ao);
        }
        #pragma unroll
        for (int nt = 0; nt < 4; ++nt){
            const uint32_t bo = (uint32_t)((warp_n*32 + nt*8 + brow)*ROWB + (kk + bcol)*2);
            LDM2(bh[nt], sb + OFF_BH + bo);
            LDM2(bl[nt], sb + OFF_BL + bo);
        }
        #pragma unroll
        for (int mt = 0; mt < 4; ++mt)
            #pragma unroll
            for (int nt = 0; nt < 4; ++nt)
                MMA_BF16(acc[mt][nt], ah[mt], bh[nt]);
        #pragma unroll
        for (int mt = 0; mt < 4; ++mt)
            #pragma unroll
            for (int nt = 0; nt < 4; ++nt)
                MMA_BF16(acc[mt][nt], ah[mt], bl[nt]);
        #pragma unroll
        for (int mt = 0; mt < 4; ++mt)
            #pragma unroll
            for (int nt = 0; nt < 4; ++nt)
                MMA_BF16(acc[mt][nt], al[mt], bh[nt]);
    }
}

// ---------------------------------------------------------------------------
// GEMM core: acc = A[128,K] @ B^T[64,K]  (128x64 CTA tile, 3-stage pipeline)
// ---------------------------------------------------------------------------
__device__ __forceinline__ void gemm_mma(
    const __nv_bfloat16* __restrict__ Ah, const __nv_bfloat16* __restrict__ Al, int lda,
    const __nv_bfloat16* __restrict__ Bh, const __nv_bfloat16* __restrict__ Bl, int ldb,
    int K, float acc[4][4][4], char* smem)
{
    const uint32_t sb = smem_u32(smem);
    const int t = threadIdx.x;
    const int lane = t & 31, wid = t >> 5;
    const int warp_m = wid & 1, warp_n = wid >> 1;

    #pragma unroll
    for (int i = 0; i < 4; ++i)
        #pragma unroll
        for (int j = 0; j < 4; ++j)
            #pragma unroll
            for (int r = 0; r < 4; ++r) acc[i][j][r] = 0.0f;

    const int nIter = K >> 5;
    issue_stage(sb, Ah, Al, lda, Bh, Bl, ldb, 0, t);
    CP_COMMIT();
    if (nIter > 1){
        issue_stage(sb + STAGE_B, Ah, Al, lda, Bh, Bl, ldb, 32, t);
        CP_COMMIT();
    }

    int buf = 0;
    for (int it = 0; it < nIter; ++it){
        if (it + 2 < nIter){
            int nb = buf + 2; if (nb >= NSTAGE) nb -= NSTAGE;
            issue_stage(sb + nb*STAGE_B, Ah, Al, lda, Bh, Bl, ldb, (it+2)*32, t);
            CP_COMMIT();
            CP_WAIT2();
        } else if (it + 1 < nIter){
            CP_WAIT1();
        } else {
            CP_WAIT0();
        }
        __syncthreads();
        compute_stage(sb + buf*STAGE_B, warp_m, warp_n, lane, acc);
        __syncthreads();
        if (++buf == NSTAGE) buf = 0;
    }
}

// ---------------------------------------------------------------------------
// prep kernel: blocks [0,128) = distance+weighting; [128, 4736) = transpose.
// dist blocks first so they start immediately; transpose backfills.
// ---------------------------------------------------------------------------
__device__ void dist_body(const float* __restrict__ xv, const float* __restrict__ xa, int q)
{
    const int dir = q & 1;
    const int b   = (q >> 1) & 1;
    const int i0  = (q >> 2) * 8;
    const float* self  = dir ? xa : xv;
    const float* other = dir ? xv : xa;
    __nv_bfloat16* ohi = g_xwhi + (size_t)dir*MM*DD;
    __nv_bfloat16* olo = g_xwlo + (size_t)dir*MM*DD;

    const int t = threadIdx.x;
    const ull* sb_ = reinterpret_cast<const ull*>(self  + (size_t)b*NTOK*DD);
    const ull* ob_ = reinterpret_cast<const ull*>(other + (size_t)b*NTOK*DD);

    ull a[8], acc[8];
    #pragma unroll
    for (int r = 0; r < 8; ++r){
        a[r] = sb_[(size_t)(i0+r)*256 + t];
        acc[r] = 0ull;
    }
    const ull SGN = 0x8000000080000000ull;
    const ull ABS = 0x7FFFFFFF7FFFFFFFull;

    #pragma unroll 2
    for (int j = 0; j < NTOK; ++j){
        const ull on = ob_[(size_t)j*256 + t] ^ SGN;
        #pragma unroll
        for (int r = 0; r < 8; ++r){
            ull d = addx2(a[r], on);
            d &= ABS;
            acc[r] = addx2(acc[r], d);
        }
    }

    __shared__ float red[8][256];
    #pragma unroll
    for (int r = 0; r < 8; ++r){
        float2 p = unpk2(acc[r]);
        red[r][t] = p.x + p.y;
    }
    __syncthreads();
    for (int s = 128; s > 0; s >>= 1){
        if (t < s){
            #pragma unroll
            for (int r = 0; r < 8; ++r) red[r][t] += red[r][t+s];
        }
        __syncthreads();
    }

    const float inv = 1.0f / (float)NTOK;
    #pragma unroll
    for (int r = 0; r < 8; ++r){
        const float s = red[r][0] * inv;
        const float2 av = unpk2(a[r]);
        const float v0 = av.x * s, v1 = av.y * s;
        __nv_bfloat16 h0, l0, h1, l1;
        split_bf16(v0, h0, l0);
        split_bf16(v1, h1, l1);
        __nv_bfloat162 ph; ph.x = h0; ph.y = h1;
        __nv_bfloat162 pl; pl.x = l0; pl.y = l1;
        const size_t o = (size_t)(b*NTOK + i0 + r)*DD + 2*t;
        *reinterpret_cast<__nv_bfloat162*>(ohi + o) = ph;
        *reinterpret_cast<__nv_bfloat162*>(olo + o) = pl;
    }
}

__device__ void transpose_body(const float* __restrict__ W1v, const float* __restrict__ W1a,
                               const float* __restrict__ Wmv, const float* __restrict__ Wma,
                               const float* __restrict__ Wout, int bid)
{
    const float* src; __nv_bfloat16 *dhi, *dlo; int R, C, ti;
    if (bid < 1024)      { src=W1v;  dhi=g_w1thi;        dlo=g_w1tlo;        R=512;  C=2048; ti=bid; }
    else if (bid < 2048) { src=W1a;  dhi=g_w1thi+HH*DD;  dlo=g_w1tlo+HH*DD;  R=512;  C=2048; ti=bid-1024; }
    else if (bid < 3072) { src=Wmv;  dhi=g_wmthi;        dlo=g_wmtlo;        R=2048; C=512;  ti=bid-2048; }
    else if (bid < 4096) { src=Wma;  dhi=g_wmthi+DD*HH;  dlo=g_wmtlo+DD*HH;  R=2048; C=512;  ti=bid-3072; }
    else                 { src=Wout; dhi=g_wothi;        dlo=g_wotlo;        R=1024; C=512;  ti=bid-4096; }

    const int TC_ = C >> 5;
    const int c0 = (ti % TC_) * 32;
    const int r0 = (ti / TC_) * 32;

    __shared__ float s[32][33];
    const int tx = threadIdx.x & 31;
    const int ty = threadIdx.x >> 5;

    #pragma unroll
    for (int i = 0; i < 4; ++i)
        s[ty + 8*i][tx] = src[(size_t)(r0 + ty + 8*i)*C + c0 + tx];
    __syncthreads();

    #pragma unroll
    for (int i = 0; i < 4; ++i){
        const int cc = ty + 8*i;
        const float v = s[tx][cc];
        __nv_bfloat16 h, l;
        split_bf16(v, h, l);
        dhi[(size_t)(c0 + cc)*R + r0 + tx] = h;
        dlo[(size_t)(c0 + cc)*R + r0 + tx] = l;
    }
}

__global__ void __launch_bounds__(256)
prep_kernel(const float* __restrict__ xv, const float* __restrict__ xa,
            const float* __restrict__ W1v, const float* __restrict__ W1a,
            const float* __restrict__ Wmv, const float* __restrict__ Wma,
            const float* __restrict__ Wout)
{
    if (blockIdx.x < 128) dist_body(xv, xa, blockIdx.x);
    else                  transpose_body(W1v, W1a, Wmv, Wma, Wout, blockIdx.x - 128);
}

// ---------------------------------------------------------------------------
// G1: h1 = gelu(xw @ W1 + b1) -> bf16 hi/lo.  grid (32, 4, 2), 128 thr.
// ---------------------------------------------------------------------------
__global__ void __launch_bounds__(128)
g1_mma(const float* __restrict__ b1v, const float* __restrict__ b1a)
{
    extern __shared__ char smem[];
    const int side = blockIdx.z;
    const int n0 = blockIdx.x * 64, m0 = blockIdx.y * 128;

    const __nv_bfloat16* Ah = g_xwhi  + (size_t)side*MM*DD + (size_t)m0*DD;
    const __nv_bfloat16* Al = g_xwlo  + (size_t)side*MM*DD + (size_t)m0*DD;
    const __nv_bfloat16* Bh = g_w1thi + (size_t)side*HH*DD + (size_t)n0*DD;
    const __nv_bfloat16* Bl = g_w1tlo + (size_t)side*HH*DD + (size_t)n0*DD;

    float acc[4][4][4];
    gemm_mma(Ah, Al, DD, Bh, Bl, DD, DD, acc, smem);

    const float* bias = side ? b1a : b1v;
    __nv_bfloat16* Hh = g_h1hi + (size_t)side*MM*HH;
    __nv_bfloat16* Hl = g_h1lo + (size_t)side*MM*HH;

    const int lane = threadIdx.x & 31, wid = threadIdx.x >> 5;
    const int warp_m = wid & 1, warp_n = wid >> 1;

    #pragma unroll
    for (int mt = 0; mt < 4; ++mt){
        #pragma unroll
        for (int nt = 0; nt < 4; ++nt){
            const int row = m0 + warp_m*64 + mt*16 + (lane >> 2);
            const int col = n0 + warp_n*32 + nt*8  + (lane & 3)*2;
            const float bb0 = bias[col], bb1 = bias[col+1];
            #pragma unroll
            for (int h = 0; h < 2; ++h){
                const int rr = row + h*8;
                float v0 = gelu1(acc[mt][nt][2*h]   + bb0);
                float v1 = gelu1(acc[mt][nt][2*h+1] + bb1);
                __nv_bfloat16 h0, l0, h1, l1;
                split_bf16(v0, h0, l0);
                split_bf16(v1, h1, l1);
                __nv_bfloat162 ph; ph.x = h0; ph.y = h1;
                __nv_bfloat162 pl; pl.x = l0; pl.y = l1;
                *reinterpret_cast<__nv_bfloat162*>(Hh + (size_t)rr*HH + col) = ph;
                *reinterpret_cast<__nv_bfloat162*>(Hl + (size_t)rr*HH + col) = pl;
            }
        }
    }
}

// ---------------------------------------------------------------------------
// G2: p2[side][sp] = h1[:, sp*512:(sp+1)*512] @ WmT.  grid (8, 4, 8), 128 thr.
// ---------------------------------------------------------------------------
__global__ void __launch_bounds__(128)
g2_mma()
{
    extern __shared__ char smem[];
    const int side = blockIdx.z & 1;
    const int sp   = blockIdx.z >> 1;
    const int n0 = blockIdx.x * 64, m0 = blockIdx.y * 128;
    const int ko = sp * 512;

    const __nv_bfloat16* Ah = g_h1hi  + (size_t)side*MM*HH + (size_t)m0*HH + ko;
    const __nv_bfloat16* Al = g_h1lo  + (size_t)side*MM*HH + (size_t)m0*HH + ko;
    const __nv_bfloat16* Bh = g_wmthi + (size_t)side*DD*HH + (size_t)n0*HH + ko;
    const __nv_bfloat16* Bl = g_wmtlo + (size_t)side*DD*HH + (size_t)n0*HH + ko;

    float acc[4][4][4];
    gemm_mma(Ah, Al, HH, Bh, Bl, HH, 512, acc, smem);

    float* C = g_p2 + (size_t)(side*4 + sp)*MM*DD;
    const int lane = threadIdx.x & 31, wid = threadIdx.x >> 5;
    const int warp_m = wid & 1, warp_n = wid >> 1;

    #pragma unroll
    for (int mt = 0; mt < 4; ++mt){
        #pragma unroll
        for (int nt = 0; nt < 4; ++nt){
            const int row = m0 + warp_m*64 + mt*16 + (lane >> 2);
            const int col = n0 + warp_n*32 + nt*8  + (lane & 3)*2;
            #pragma unroll
            for (int h = 0; h < 2; ++h){
                *reinterpret_cast<float2*>(C + (size_t)(row + h*8)*DD + col) =
                    make_float2(acc[mt][nt][2*h], acc[mt][nt][2*h+1]);
            }
        }
    }
}

// ---------------------------------------------------------------------------
// Reduce G2 partials + bias -> comb bf16 hi/lo.
// ---------------------------------------------------------------------------
__global__ void __launch_bounds__(256)
reduce_g2(const float* __restrict__ bmv, const float* __restrict__ bma)
{
    const int q = blockIdx.x * 256 + threadIdx.x;   // [0, 131072)
    const int n = (q & 255) * 4;                    // [0, 1024)
    const int m = q >> 8;                           // [0, 512)
    const int side = n >> 9;
    const int c = n & 511;

    const float* P = g_p2 + (size_t)side*4*MM*DD + (size_t)m*DD + c;
    float4 v0 = *reinterpret_cast<const float4*>(P);
    float4 v1 = *reinterpret_cast<const float4*>(P + MM*DD);
    float4 v2 = *reinterpret_cast<const float4*>(P + 2*MM*DD);
    float4 v3 = *reinterpret_cast<const float4*>(P + 3*MM*DD);
    const float* bias = side ? bma : bmv;
    float4 bb = *reinterpret_cast<const float4*>(bias + c);

    float v[4];
    v[0] = v0.x + v1.x + v2.x + v3.x + bb.x;
    v[1] = v0.y + v1.y + v2.y + v3.y + bb.y;
    v[2] = v0.z + v1.z + v2.z + v3.z + bb.z;
    v[3] = v0.w + v1.w + v2.w + v3.w + bb.w;

    const size_t o = (size_t)m*(2*DD) + n;
    #pragma unroll
    for (int i = 0; i < 4; i += 2){
        __nv_bfloat16 h0, l0, h1, l1;
        split_bf16(v[i],   h0, l0);
        split_bf16(v[i+1], h1, l1);
        __nv_bfloat162 ph; ph.x = h0; ph.y = h1;
        __nv_bfloat162 pl; pl.x = l0; pl.y = l1;
        *reinterpret_cast<__nv_bfloat162*>(g_combhi + o + i) = ph;
        *reinterpret_cast<__nv_bfloat162*>(g_comblo + o + i) = pl;
    }
}

// ---------------------------------------------------------------------------
// G3: p3[sp] = comb[:, sp*128:(sp+1)*128] @ WoutT.  grid (8, 4, 8), 128 thr.
// ---------------------------------------------------------------------------
__global__ void __launch_bounds__(128)
g3_mma()
{
    extern __shared__ char smem[];
    const int sp = blockIdx.z;
    const int n0 = blockIdx.x * 64, m0 = blockIdx.y * 128;
    const int ko = sp * 128;

    const __nv_bfloat16* Ah = g_combhi + (size_t)m0*(2*DD) + ko;
    const __nv_bfloat16* Al = g_comblo + (size_t)m0*(2*DD) + ko;
    const __nv_bfloat16* Bh = g_wothi  + (size_t)n0*(2*DD) + ko;
    const __nv_bfloat16* Bl = g_wotlo  + (size_t)n0*(2*DD) + ko;

    float acc[4][4][4];
    gemm_mma(Ah, Al, 2*DD, Bh, Bl, 2*DD, 128, acc, smem);

    float* C = g_p3 + (size_t)sp*MM*DD;
    const int lane = threadIdx.x & 31, wid = threadIdx.x >> 5;
    const int warp_m = wid & 1, warp_n = wid >> 1;

    #pragma unroll
    for (int mt = 0; mt < 4; ++mt){
        #pragma unroll
        for (int nt = 0; nt < 4; ++nt){
            const int row = m0 + warp_m*64 + mt*16 + (lane >> 2);
            const int col = n0 + warp_n*32 + nt*8  + (lane & 3)*2;
            #pragma unroll
            for (int h = 0; h < 2; ++h){
                *reinterpret_cast<float2*>(C + (size_t)(row + h*8)*DD + col) =
                    make_float2(acc[mt][nt][2*h], acc[mt][nt][2*h+1]);
            }
        }
    }
}

// ---------------------------------------------------------------------------
// Reduce G3 partials + bout -> out fp32.
// ---------------------------------------------------------------------------
__global__ void __launch_bounds__(256)
reduce_g3(float* __restrict__ out, const float* __restrict__ bout)
{
    const int q = blockIdx.x * 256 + threadIdx.x;   // [0, 65536)
    const int n = (q & 127) * 4;
    const int m = q >> 7;
    const size_t o = (size_t)m*DD + n;

    float4 r = *reinterpret_cast<const float4*>(bout + n);
    #pragma unroll
    for (int sp = 0; sp < 8; ++sp){
        float4 v = *reinterpret_cast<const float4*>(g_p3 + (size_t)sp*MM*DD + o);
        r.x += v.x; r.y += v.y; r.z += v.z; r.w += v.w;
    }
    *reinterpret_cast<float4*>(out + o) = r;
}

// ---------------------------------------------------------------------------
extern "C" void kernel_launch(void* const* d_in, const int* in_sizes, int n_in,
                              void* d_out, int out_size)
{
    (void)in_sizes; (void)n_in; (void)out_size;

    const float* x_v  = (const float*)d_in[0];
    const float* x_a  = (const float*)d_in[1];
    const float* W1v  = (const float*)d_in[2];
    const float* b1v  = (const float*)d_in[3];
    const float* W1a  = (const float*)d_in[4];
    const float* b1a  = (const float*)d_in[5];
    const float* Wmv  = (const float*)d_in[6];
    const float* bmv  = (const float*)d_in[7];
    const float* Wma  = (const float*)d_in[8];
    const float* bma  = (const float*)d_in[9];
    const float* Wout = (const float*)d_in[10];
    const float* bout = (const float*)d_in[11];
    float* out = (float*)d_out;

    cudaFuncSetAttribute(g1_mma, cudaFuncAttributeMaxDynamicSharedMemorySize, SMEM_BYTES);
    cudaFuncSetAttribute(g2_mma, cudaFuncAttributeMaxDynamicSharedMemorySize, SMEM_BYTES);
    cudaFuncSetAttribute(g3_mma, cudaFuncAttributeMaxDynamicSharedMemorySize, SMEM_BYTES);

    // 1) fused prep: dist blocks [0,128) + weight transpose/split [128,4736)
    prep_kernel<<<4736, 256>>>(x_v, x_a, W1v, W1a, Wmv, Wma, Wout);

    // 2) G1: h1 = gelu(xw @ W1 + b1) -> bf16 split   (256 CTAs)
    g1_mma<<<dim3(HH/64, MM/128, 2), 128, SMEM_BYTES>>>(b1v, b1a);

    // 3) G2: split-K=4 partials per side             (256 CTAs)
    g2_mma<<<dim3(DD/64, MM/128, 8), 128, SMEM_BYTES>>>();

    // 4) comb = sum partials + bias -> bf16 split
    reduce_g2<<<512, 256>>>(bmv, bma);

    // 5) G3: split-K=8 partials                      (256 CTAs)
    g3_mma<<<dim3(DD/64, MM/128, 8), 128, SMEM_BYTES>>>();

    // 6) out = sum partials + bout
    reduce_g3<<<256, 256>>>(out, bout);
}

// round 6
// speedup vs baseline: 1.0768x; 1.0768x over previous
#include <cuda_runtime.h>
#include <cuda_bf16.h>
#include <cstdint>

#define BB 2
#define NTOK 256
#define DD 512
#define HH 2048
#define MM (BB*NTOK)   /* 512 rows total */

typedef unsigned long long ull;

// ---------------- scratch (device globals: allocation-free) ----------------
__device__ __nv_bfloat16 g_xwhi[2*MM*DD],  g_xwlo[2*MM*DD];     // [side][m][k]
__device__ __nv_bfloat16 g_w1thi[2*HH*DD], g_w1tlo[2*HH*DD];    // [side][n=2048][k=512]
__device__ __nv_bfloat16 g_wmthi[2*DD*HH], g_wmtlo[2*DD*HH];    // [side][n=512][k=2048]
__device__ __nv_bfloat16 g_wothi[DD*2*DD], g_wotlo[DD*2*DD];    // [n=512][k=1024]
__device__ __nv_bfloat16 g_h1hi[2*MM*HH],  g_h1lo[2*MM*HH];     // [side][m][k=2048]
__device__ float         g_p2[8*MM*DD];                         // [side*4+sp][m][n]
__device__ __nv_bfloat16 g_combhi[MM*2*DD], g_comblo[MM*2*DD];  // [m][k=1024]
__device__ float         g_p3[8*MM*DD];                         // [sp][m][n]

// ---------------- helpers ----------------
__device__ __forceinline__ uint32_t smem_u32(const void* p){
    uint32_t a;
    asm("{ .reg .u64 t; cvta.to.shared.u64 t, %1; cvt.u32.u64 %0, t; }" : "=r"(a) : "l"(p));
    return a;
}
__device__ __forceinline__ ull addx2(ull a, ull b){
    ull d; asm("add.rn.f32x2 %0, %1, %2;" : "=l"(d) : "l"(a), "l"(b)); return d;
}
__device__ __forceinline__ float2 unpk2(ull v){
    uint32_t lo, hi;
    asm("mov.b64 {%0, %1}, %2;" : "=r"(lo), "=r"(hi) : "l"(v));
    return make_float2(__uint_as_float(lo), __uint_as_float(hi));
}
__device__ __forceinline__ void split_bf16(float v, __nv_bfloat16& h, __nv_bfloat16& l){
    h = __float2bfloat16(v);
    l = __float2bfloat16(v - __bfloat162float(h));
}
__device__ __forceinline__ float gelu1(float x){
    return 0.5f*x*(1.0f + erff(x*0.70710678118654752f));
}

// ---------------- cp.async / ldmatrix / mma (baseline sm_80+ PTX) ----------
__device__ __forceinline__ void cp16(uint32_t s, const void* g){
    asm volatile("cp.async.ca.shared.global [%0], [%1], 16;" :: "r"(s), "l"(g) : "memory");
}
#define CP_COMMIT() asm volatile("cp.async.commit_group;" ::: "memory")
#define CP_WAIT2()  asm volatile("cp.async.wait_group 2;" ::: "memory")
#define CP_WAIT1()  asm volatile("cp.async.wait_group 1;" ::: "memory")
#define CP_WAIT0()  asm volatile("cp.async.wait_group 0;" ::: "memory")

#define LDM4(r, addr) \
    asm volatile("ldmatrix.sync.aligned.m8n8.x4.shared.b16 {%0,%1,%2,%3}, [%4];" \
        : "=r"((r)[0]), "=r"((r)[1]), "=r"((r)[2]), "=r"((r)[3]) : "r"(addr))
#define LDM2(r, addr) \
    asm volatile("ldmatrix.sync.aligned.m8n8.x2.shared.b16 {%0,%1}, [%2];" \
        : "=r"((r)[0]), "=r"((r)[1]) : "r"(addr))

#define MMA_BF16(d, a, b) \
    asm volatile("mma.sync.aligned.m16n8k16.row.col.f32.bf16.bf16.f32 " \
        "{%0,%1,%2,%3}, {%4,%5,%6,%7}, {%8,%9}, {%0,%1,%2,%3};" \
        : "+f"((d)[0]), "+f"((d)[1]), "+f"((d)[2]), "+f"((d)[3]) \
        : "r"((a)[0]), "r"((a)[1]), "r"((a)[2]), "r"((a)[3]), \
          "r"((b)[0]), "r"((b)[1]))

// CTA tile 128(M) x 128(N), templated BK. Row bytes = 2*BK + 16 pad
// (multiple of 16 -> cp.async-aligned; stride mod 128 = 16/ -> 8 ldmatrix rows
// hit 8 distinct 16B slots -> conflict-free). 3-stage cp.async pipeline.
#define NSTAGE 3

template<int BKT>
__device__ __forceinline__ void issue_stage(
    uint32_t sb,
    const __nv_bfloat16* __restrict__ Ah, const __nv_bfloat16* __restrict__ Al, int lda,
    const __nv_bfloat16* __restrict__ Bh, const __nv_bfloat16* __restrict__ Bl, int ldb,
    int k0, int t)
{
    constexpr int ROWB = 2*BKT + 16;
    constexpr int TILE = 128*ROWB;
    const int row = t >> 1, half = t & 1;
    const uint32_t so = (uint32_t)(row*ROWB + half*BKT);
    const size_t ga = (size_t)row*lda + k0 + half*(BKT/2);
    const size_t gb = (size_t)row*ldb + k0 + half*(BKT/2);
    #pragma unroll
    for (int i = 0; i < BKT/16; ++i){
        cp16(sb +          so + i*16, Ah + ga + i*8);
        cp16(sb +   TILE + so + i*16, Al + ga + i*8);
        cp16(sb + 2*TILE + so + i*16, Bh + gb + i*8);
        cp16(sb + 3*TILE + so + i*16, Bl + gb + i*8);
    }
}

// warp grid 2(m) x 4(n), warp tile 64x32; register double-buffered fragments.
template<int BKT>
__device__ __forceinline__ void compute_stage(
    uint32_t sb, int warp_m, int warp_n, int lane, float acc[4][4][4])
{
    constexpr int ROWB = 2*BKT + 16;
    constexpr int TILE = 128*ROWB;
    constexpr int NKK  = BKT/16;
    const int arow = lane & 15;
    const int acol = (lane >> 4) * 8;
    const int brow = lane & 7;
    const int bcol = ((lane >> 3) & 1) * 8;

    uint32_t ah[2][4][4], al[2][4][4], bh[2][4][2], bl[2][4][2];

    auto load_frags = [&](int kk, int b){
        #pragma unroll
        for (int mt = 0; mt < 4; ++mt){
            const uint32_t ao = (uint32_t)((warp_m*64 + mt*16 + arow)*ROWB + (kk*16 + acol)*2);
            LDM4(ah[b][mt], sb + ao);
            LDM4(al[b][mt], sb + TILE + ao);
        }
        #pragma unroll
        for (int nt = 0; nt < 4; ++nt){
            const uint32_t bo = (uint32_t)((warp_n*32 + nt*8 + brow)*ROWB + (kk*16 + bcol)*2);
            LDM2(bh[b][nt], sb + 2*TILE + bo);
            LDM2(bl[b][nt], sb + 3*TILE + bo);
        }
    };

    load_frags(0, 0);
    #pragma unroll
    for (int kk = 0; kk < NKK; ++kk){
        const int c = kk & 1;
        if (kk + 1 < NKK) load_frags(kk + 1, c ^ 1);
        #pragma unroll
        for (int mt = 0; mt < 4; ++mt)
            #pragma unroll
            for (int nt = 0; nt < 4; ++nt)
                MMA_BF16(acc[mt][nt], ah[c][mt], bh[c][nt]);
        #pragma unroll
        for (int mt = 0; mt < 4; ++mt)
            #pragma unroll
            for (int nt = 0; nt < 4; ++nt)
                MMA_BF16(acc[mt][nt], ah[c][mt], bl[c][nt]);
        #pragma unroll
        for (int mt = 0; mt < 4; ++mt)
            #pragma unroll
            for (int nt = 0; nt < 4; ++nt)
                MMA_BF16(acc[mt][nt], al[c][mt], bh[c][nt]);
    }
}

// GEMM core: acc = A[128,K] @ B^T[128,K]  (128x128 CTA tile, 3-stage pipeline)
// requires K/BKT >= 2.
template<int BKT>
__device__ __forceinline__ void gemm_mma(
    const __nv_bfloat16* __restrict__ Ah, const __nv_bfloat16* __restrict__ Al, int lda,
    const __nv_bfloat16* __restrict__ Bh, const __nv_bfloat16* __restrict__ Bl, int ldb,
    int K, float acc[4][4][4], char* smem)
{
    constexpr int ROWB  = 2*BKT + 16;
    constexpr int STAGE = 4*128*ROWB;
    const uint32_t sb = smem_u32(smem);
    const int t = threadIdx.x;
    const int lane = t & 31, wid = t >> 5;
    const int warp_m = wid & 1, warp_n = wid >> 1;

    #pragma unroll
    for (int i = 0; i < 4; ++i)
        #pragma unroll
        for (int j = 0; j < 4; ++j)
            #pragma unroll
            for (int r = 0; r < 4; ++r) acc[i][j][r] = 0.0f;

    const int nIter = K / BKT;
    issue_stage<BKT>(sb, Ah, Al, lda, Bh, Bl, ldb, 0, t);
    CP_COMMIT();
    issue_stage<BKT>(sb + STAGE, Ah, Al, lda, Bh, Bl, ldb, BKT, t);
    CP_COMMIT();

    int buf = 0;
    for (int it = 0; it < nIter; ++it){
        if (it + 2 < nIter){
            int nb = buf + 2; if (nb >= NSTAGE) nb -= NSTAGE;
            issue_stage<BKT>(sb + nb*STAGE, Ah, Al, lda, Bh, Bl, ldb, (it+2)*BKT, t);
            CP_COMMIT();
            CP_WAIT2();
        } else if (it + 1 < nIter){
            CP_WAIT1();
        } else {
            CP_WAIT0();
        }
        __syncthreads();
        compute_stage<BKT>(sb + buf*STAGE, warp_m, warp_n, lane, acc);
        __syncthreads();
        if (++buf == NSTAGE) buf = 0;
    }
}

#define SMEM_G12 (NSTAGE*4*128*(2*64+16))   /* BK=64: 221184 */
#define SMEM_G3  (NSTAGE*4*128*(2*32+16))   /* BK=32: 122880 */

// ---------------------------------------------------------------------------
// prep kernel: blocks [0,128) = distance+weighting; [128, 4736) = transpose.
// ---------------------------------------------------------------------------
__device__ void dist_body(const float* __restrict__ xv, const float* __restrict__ xa, int q)
{
    const int dir = q & 1;
    const int b   = (q >> 1) & 1;
    const int i0  = (q >> 2) * 8;
    const float* self  = dir ? xa : xv;
    const float* other = dir ? xv : xa;
    __nv_bfloat16* ohi = g_xwhi + (size_t)dir*MM*DD;
    __nv_bfloat16* olo = g_xwlo + (size_t)dir*MM*DD;

    const int t = threadIdx.x;
    const ull* sb_ = reinterpret_cast<const ull*>(self  + (size_t)b*NTOK*DD);
    const ull* ob_ = reinterpret_cast<const ull*>(other + (size_t)b*NTOK*DD);

    ull a[8], acc[8];
    #pragma unroll
    for (int r = 0; r < 8; ++r){
        a[r] = sb_[(size_t)(i0+r)*256 + t];
        acc[r] = 0ull;
    }
    const ull SGN = 0x8000000080000000ull;
    const ull ABS = 0x7FFFFFFF7FFFFFFFull;

    #pragma unroll 2
    for (int j = 0; j < NTOK; ++j){
        const ull on = ob_[(size_t)j*256 + t] ^ SGN;
        #pragma unroll
        for (int r = 0; r < 8; ++r){
            ull d = addx2(a[r], on);
            d &= ABS;
            acc[r] = addx2(acc[r], d);
        }
    }

    __shared__ float red[8][256];
    #pragma unroll
    for (int r = 0; r < 8; ++r){
        float2 p = unpk2(acc[r]);
        red[r][t] = p.x + p.y;
    }
    __syncthreads();
    for (int s = 128; s > 0; s >>= 1){
        if (t < s){
            #pragma unroll
            for (int r = 0; r < 8; ++r) red[r][t] += red[r][t+s];
        }
        __syncthreads();
    }

    const float inv = 1.0f / (float)NTOK;
    #pragma unroll
    for (int r = 0; r < 8; ++r){
        const float s = red[r][0] * inv;
        const float2 av = unpk2(a[r]);
        const float v0 = av.x * s, v1 = av.y * s;
        __nv_bfloat16 h0, l0, h1, l1;
        split_bf16(v0, h0, l0);
        split_bf16(v1, h1, l1);
        __nv_bfloat162 ph; ph.x = h0; ph.y = h1;
        __nv_bfloat162 pl; pl.x = l0; pl.y = l1;
        const size_t o = (size_t)(b*NTOK + i0 + r)*DD + 2*t;
        *reinterpret_cast<__nv_bfloat162*>(ohi + o) = ph;
        *reinterpret_cast<__nv_bfloat162*>(olo + o) = pl;
    }
}

__device__ void transpose_body(const float* __restrict__ W1v, const float* __restrict__ W1a,
                               const float* __restrict__ Wmv, const float* __restrict__ Wma,
                               const float* __restrict__ Wout, int bid)
{
    const float* src; __nv_bfloat16 *dhi, *dlo; int R, C, ti;
    if (bid < 1024)      { src=W1v;  dhi=g_w1thi;        dlo=g_w1tlo;        R=512;  C=2048; ti=bid; }
    else if (bid < 2048) { src=W1a;  dhi=g_w1thi+HH*DD;  dlo=g_w1tlo+HH*DD;  R=512;  C=2048; ti=bid-1024; }
    else if (bid < 3072) { src=Wmv;  dhi=g_wmthi;        dlo=g_wmtlo;        R=2048; C=512;  ti=bid-2048; }
    else if (bid < 4096) { src=Wma;  dhi=g_wmthi+DD*HH;  dlo=g_wmtlo+DD*HH;  R=2048; C=512;  ti=bid-3072; }
    else                 { src=Wout; dhi=g_wothi;        dlo=g_wotlo;        R=1024; C=512;  ti=bid-4096; }

    const int TC_ = C >> 5;
    const int c0 = (ti % TC_) * 32;
    const int r0 = (ti / TC_) * 32;

    __shared__ float s[32][33];
    const int tx = threadIdx.x & 31;
    const int ty = threadIdx.x >> 5;

    #pragma unroll
    for (int i = 0; i < 4; ++i)
        s[ty + 8*i][tx] = src[(size_t)(r0 + ty + 8*i)*C + c0 + tx];
    __syncthreads();

    #pragma unroll
    for (int i = 0; i < 4; ++i){
        const int cc = ty + 8*i;
        const float v = s[tx][cc];
        __nv_bfloat16 h, l;
        split_bf16(v, h, l);
        dhi[(size_t)(c0 + cc)*R + r0 + tx] = h;
        dlo[(size_t)(c0 + cc)*R + r0 + tx] = l;
    }
}

__global__ void __launch_bounds__(256)
prep_kernel(const float* __restrict__ xv, const float* __restrict__ xa,
            const float* __restrict__ W1v, const float* __restrict__ W1a,
            const float* __restrict__ Wmv, const float* __restrict__ Wma,
            const float* __restrict__ Wout)
{
    if (blockIdx.x < 128) dist_body(xv, xa, blockIdx.x);
    else                  transpose_body(W1v, W1a, Wmv, Wma, Wout, blockIdx.x - 128);
}

// ---------------------------------------------------------------------------
// G1: h1 = gelu(xw @ W1 + b1) -> bf16 hi/lo.  grid (16, 4, 2), 256 thr.
// ---------------------------------------------------------------------------
__global__ void __launch_bounds__(256)
g1_mma(const float* __restrict__ b1v, const float* __restrict__ b1a)
{
    extern __shared__ char smem[];
    const int side = blockIdx.z;
    const int n0 = blockIdx.x * 128, m0 = blockIdx.y * 128;

    const __nv_bfloat16* Ah = g_xwhi  + (size_t)side*MM*DD + (size_t)m0*DD;
    const __nv_bfloat16* Al = g_xwlo  + (size_t)side*MM*DD + (size_t)m0*DD;
    const __nv_bfloat16* Bh = g_w1thi + (size_t)side*HH*DD + (size_t)n0*DD;
    const __nv_bfloat16* Bl = g_w1tlo + (size_t)side*HH*DD + (size_t)n0*DD;

    float acc[4][4][4];
    gemm_mma<64>(Ah, Al, DD, Bh, Bl, DD, DD, acc, smem);

    const float* bias = side ? b1a : b1v;
    __nv_bfloat16* Hh = g_h1hi + (size_t)side*MM*HH;
    __nv_bfloat16* Hl = g_h1lo + (size_t)side*MM*HH;

    const int lane = threadIdx.x & 31, wid = threadIdx.x >> 5;
    const int warp_m = wid & 1, warp_n = wid >> 1;

    #pragma unroll
    for (int mt = 0; mt < 4; ++mt){
        #pragma unroll
        for (int nt = 0; nt < 4; ++nt){
            const int row = m0 + warp_m*64 + mt*16 + (lane >> 2);
            const int col = n0 + warp_n*32 + nt*8  + (lane & 3)*2;
            const float bb0 = bias[col], bb1 = bias[col+1];
            #pragma unroll
            for (int h = 0; h < 2; ++h){
                const int rr = row + h*8;
                float v0 = gelu1(acc[mt][nt][2*h]   + bb0);
                float v1 = gelu1(acc[mt][nt][2*h+1] + bb1);
                __nv_bfloat16 h0, l0, h1, l1;
                split_bf16(v0, h0, l0);
                split_bf16(v1, h1, l1);
                __nv_bfloat162 ph; ph.x = h0; ph.y = h1;
                __nv_bfloat162 pl; pl.x = l0; pl.y = l1;
                *reinterpret_cast<__nv_bfloat162*>(Hh + (size_t)rr*HH + col) = ph;
                *reinterpret_cast<__nv_bfloat162*>(Hl + (size_t)rr*HH + col) = pl;
            }
        }
    }
}

// ---------------------------------------------------------------------------
// G2: p2[side][sp] = h1[:, sp*512:(sp+1)*512] @ WmT.  grid (4, 4, 8), 256 thr.
// ---------------------------------------------------------------------------
__global__ void __launch_bounds__(256)
g2_mma()
{
    extern __shared__ char smem[];
    const int side = blockIdx.z & 1;
    const int sp   = blockIdx.z >> 1;
    const int n0 = blockIdx.x * 128, m0 = blockIdx.y * 128;
    const int ko = sp * 512;

    const __nv_bfloat16* Ah = g_h1hi  + (size_t)side*MM*HH + (size_t)m0*HH + ko;
    const __nv_bfloat16* Al = g_h1lo  + (size_t)side*MM*HH + (size_t)m0*HH + ko;
    const __nv_bfloat16* Bh = g_wmthi + (size_t)side*DD*HH + (size_t)n0*HH + ko;
    const __nv_bfloat16* Bl = g_wmtlo + (size_t)side*DD*HH + (size_t)n0*HH + ko;

    float acc[4][4][4];
    gemm_mma<64>(Ah, Al, HH, Bh, Bl, HH, 512, acc, smem);

    float* C = g_p2 + (size_t)(side*4 + sp)*MM*DD;
    const int lane = threadIdx.x & 31, wid = threadIdx.x >> 5;
    const int warp_m = wid & 1, warp_n = wid >> 1;

    #pragma unroll
    for (int mt = 0; mt < 4; ++mt){
        #pragma unroll
        for (int nt = 0; nt < 4; ++nt){
            const int row = m0 + warp_m*64 + mt*16 + (lane >> 2);
            const int col = n0 + warp_n*32 + nt*8  + (lane & 3)*2;
            #pragma unroll
            for (int h = 0; h < 2; ++h){
                *reinterpret_cast<float2*>(C + (size_t)(row + h*8)*DD + col) =
                    make_float2(acc[mt][nt][2*h], acc[mt][nt][2*h+1]);
            }
        }
    }
}

// ---------------------------------------------------------------------------
// Reduce G2 partials + bias -> comb bf16 hi/lo.
// ---------------------------------------------------------------------------
__global__ void __launch_bounds__(256)
reduce_g2(const float* __restrict__ bmv, const float* __restrict__ bma)
{
    const int q = blockIdx.x * 256 + threadIdx.x;   // [0, 131072)
    const int n = (q & 255) * 4;                    // [0, 1024)
    const int m = q >> 8;                           // [0, 512)
    const int side = n >> 9;
    const int c = n & 511;

    const float* P = g_p2 + (size_t)side*4*MM*DD + (size_t)m*DD + c;
    float4 v0 = *reinterpret_cast<const float4*>(P);
    float4 v1 = *reinterpret_cast<const float4*>(P + MM*DD);
    float4 v2 = *reinterpret_cast<const float4*>(P + 2*MM*DD);
    float4 v3 = *reinterpret_cast<const float4*>(P + 3*MM*DD);
    const float* bias = side ? bma : bmv;
    float4 bb = *reinterpret_cast<const float4*>(bias + c);

    float v[4];
    v[0] = v0.x + v1.x + v2.x + v3.x + bb.x;
    v[1] = v0.y + v1.y + v2.y + v3.y + bb.y;
    v[2] = v0.z + v1.z + v2.z + v3.z + bb.z;
    v[3] = v0.w + v1.w + v2.w + v3.w + bb.w;

    const size_t o = (size_t)m*(2*DD) + n;
    #pragma unroll
    for (int i = 0; i < 4; i += 2){
        __nv_bfloat16 h0, l0, h1, l1;
        split_bf16(v[i],   h0, l0);
        split_bf16(v[i+1], h1, l1);
        __nv_bfloat162 ph; ph.x = h0; ph.y = h1;
        __nv_bfloat162 pl; pl.x = l0; pl.y = l1;
        *reinterpret_cast<__nv_bfloat162*>(g_combhi + o + i) = ph;
        *reinterpret_cast<__nv_bfloat162*>(g_comblo + o + i) = pl;
    }
}

// ---------------------------------------------------------------------------
// G3: p3[sp] = comb[:, sp*128:(sp+1)*128] @ WoutT.  grid (4, 4, 8), 256 thr.
// ---------------------------------------------------------------------------
__global__ void __launch_bounds__(256)
g3_mma()
{
    extern __shared__ char smem[];
    const int sp = blockIdx.z;
    const int n0 = blockIdx.x * 128, m0 = blockIdx.y * 128;
    const int ko = sp * 128;

    const __nv_bfloat16* Ah = g_combhi + (size_t)m0*(2*DD) + ko;
    const __nv_bfloat16* Al = g_comblo + (size_t)m0*(2*DD) + ko;
    const __nv_bfloat16* Bh = g_wothi  + (size_t)n0*(2*DD) + ko;
    const __nv_bfloat16* Bl = g_wotlo  + (size_t)n0*(2*DD) + ko;

    float acc[4][4][4];
    gemm_mma<32>(Ah, Al, 2*DD, Bh, Bl, 2*DD, 128, acc, smem);

    float* C = g_p3 + (size_t)sp*MM*DD;
    const int lane = threadIdx.x & 31, wid = threadIdx.x >> 5;
    const int warp_m = wid & 1, warp_n = wid >> 1;

    #pragma unroll
    for (int mt = 0; mt < 4; ++mt){
        #pragma unroll
        for (int nt = 0; nt < 4; ++nt){
            const int row = m0 + warp_m*64 + mt*16 + (lane >> 2);
            const int col = n0 + warp_n*32 + nt*8  + (lane & 3)*2;
            #pragma unroll
            for (int h = 0; h < 2; ++h){
                *reinterpret_cast<float2*>(C + (size_t)(row + h*8)*DD + col) =
                    make_float2(acc[mt][nt][2*h], acc[mt][nt][2*h+1]);
            }
        }
    }
}

// ---------------------------------------------------------------------------
// Reduce G3 partials + bout -> out fp32.
// ---------------------------------------------------------------------------
__global__ void __launch_bounds__(256)
reduce_g3(float* __restrict__ out, const float* __restrict__ bout)
{
    const int q = blockIdx.x * 256 + threadIdx.x;   // [0, 65536)
    const int n = (q & 127) * 4;
    const int m = q >> 7;
    const size_t o = (size_t)m*DD + n;

    float4 r = *reinterpret_cast<const float4*>(bout + n);
    #pragma unroll
    for (int sp = 0; sp < 8; ++sp){
        float4 v = *reinterpret_cast<const float4*>(g_p3 + (size_t)sp*MM*DD + o);
        r.x += v.x; r.y += v.y; r.z += v.z; r.w += v.w;
    }
    *reinterpret_cast<float4*>(out + o) = r;
}

// ---------------------------------------------------------------------------
extern "C" void kernel_launch(void* const* d_in, const int* in_sizes, int n_in,
                              void* d_out, int out_size)
{
    (void)in_sizes; (void)n_in; (void)out_size;

    const float* x_v  = (const float*)d_in[0];
    const float* x_a  = (const float*)d_in[1];
    const float* W1v  = (const float*)d_in[2];
    const float* b1v  = (const float*)d_in[3];
    const float* W1a  = (const float*)d_in[4];
    const float* b1a  = (const float*)d_in[5];
    const float* Wmv  = (const float*)d_in[6];
    const float* bmv  = (const float*)d_in[7];
    const float* Wma  = (const float*)d_in[8];
    const float* bma  = (const float*)d_in[9];
    const float* Wout = (const float*)d_in[10];
    const float* bout = (const float*)d_in[11];
    float* out = (float*)d_out;

    cudaFuncSetAttribute(g1_mma, cudaFuncAttributeMaxDynamicSharedMemorySize, SMEM_G12);
    cudaFuncSetAttribute(g2_mma, cudaFuncAttributeMaxDynamicSharedMemorySize, SMEM_G12);
    cudaFuncSetAttribute(g3_mma, cudaFuncAttributeMaxDynamicSharedMemorySize, SMEM_G3);

    // 1) fused prep: dist blocks [0,128) + weight transpose/split [128,4736)
    prep_kernel<<<4736, 256>>>(x_v, x_a, W1v, W1a, Wmv, Wma, Wout);

    // 2) G1: h1 = gelu(xw @ W1 + b1) -> bf16 split   (128 CTAs, BK=64)
    g1_mma<<<dim3(HH/128, MM/128, 2), 256, SMEM_G12>>>(b1v, b1a);

    // 3) G2: split-K=4 partials per side             (128 CTAs, BK=64)
    g2_mma<<<dim3(DD/128, MM/128, 8), 256, SMEM_G12>>>();

    // 4) comb = sum partials + bias -> bf16 split
    reduce_g2<<<512, 256>>>(bmv, bma);

    // 5) G3: split-K=8 partials                      (128 CTAs, BK=32)
    g3_mma<<<dim3(DD/128, MM/128, 8), 256, SMEM_G3>>>();

    // 6) out = sum partials + bout
    reduce_g3<<<256, 256>>>(out, bout);
}

// round 7
// speedup vs baseline: 1.2814x; 1.1900x over previous
#include <cuda_runtime.h>
#include <cuda_bf16.h>
#include <cstdint>

#define BB 2
#define NTOK 256
#define DD 512
#define HH 2048
#define MM (BB*NTOK)   /* 512 rows total */

typedef unsigned long long ull;

// ---------------- scratch (device globals: allocation-free) ----------------
__device__ __nv_bfloat16 g_xwhi[2*MM*DD],  g_xwlo[2*MM*DD];     // [side][m][k]
__device__ __nv_bfloat16 g_w1thi[2*HH*DD], g_w1tlo[2*HH*DD];    // [side][n=2048][k=512]
__device__ __nv_bfloat16 g_wmthi[2*DD*HH], g_wmtlo[2*DD*HH];    // [side][n=512][k=2048]
__device__ __nv_bfloat16 g_wothi[DD*2*DD], g_wotlo[DD*2*DD];    // [n=512][k=1024]
__device__ __nv_bfloat16 g_h1hi[2*MM*HH],  g_h1lo[2*MM*HH];     // [side][m][k=2048]
__device__ float         g_p2[8*MM*DD];                         // [side*4+sp][m][n]
__device__ __nv_bfloat16 g_combhi[MM*2*DD], g_comblo[MM*2*DD];  // [m][k=1024]
__device__ float         g_p3[8*MM*DD];                         // [sp][m][n]
__device__ float         g_dsum[2*BB*NTOK*2];                   // [dir][b][i][half]

// ---------------- helpers ----------------
__device__ __forceinline__ uint32_t smem_u32(const void* p){
    uint32_t a;
    asm("{ .reg .u64 t; cvta.to.shared.u64 t, %1; cvt.u32.u64 %0, t; }" : "=r"(a) : "l"(p));
    return a;
}
__device__ __forceinline__ ull addx2(ull a, ull b){
    ull d; asm("add.rn.f32x2 %0, %1, %2;" : "=l"(d) : "l"(a), "l"(b)); return d;
}
__device__ __forceinline__ float2 unpk2(ull v){
    uint32_t lo, hi;
    asm("mov.b64 {%0, %1}, %2;" : "=r"(lo), "=r"(hi) : "l"(v));
    return make_float2(__uint_as_float(lo), __uint_as_float(hi));
}
__device__ __forceinline__ void split_bf16(float v, __nv_bfloat16& h, __nv_bfloat16& l){
    h = __float2bfloat16(v);
    l = __float2bfloat16(v - __bfloat162float(h));
}
__device__ __forceinline__ float gelu1(float x){
    return 0.5f*x*(1.0f + erff(x*0.70710678118654752f));
}

// ---------------- cp.async / ldmatrix / mma (baseline sm_80+ PTX) ----------
__device__ __forceinline__ void cp16(uint32_t s, const void* g){
    asm volatile("cp.async.ca.shared.global [%0], [%1], 16;" :: "r"(s), "l"(g) : "memory");
}
#define CP_COMMIT() asm volatile("cp.async.commit_group;" ::: "memory")
#define CP_WAIT1()  asm volatile("cp.async.wait_group 1;" ::: "memory")
#define CP_WAIT0()  asm volatile("cp.async.wait_group 0;" ::: "memory")

#define LDM4(r, addr) \
    asm volatile("ldmatrix.sync.aligned.m8n8.x4.shared.b16 {%0,%1,%2,%3}, [%4];" \
        : "=r"((r)[0]), "=r"((r)[1]), "=r"((r)[2]), "=r"((r)[3]) : "r"(addr))
#define LDM2(r, addr) \
    asm volatile("ldmatrix.sync.aligned.m8n8.x2.shared.b16 {%0,%1}, [%2];" \
        : "=r"((r)[0]), "=r"((r)[1]) : "r"(addr))

#define MMA_BF16(d, a, b) \
    asm volatile("mma.sync.aligned.m16n8k16.row.col.f32.bf16.bf16.f32 " \
        "{%0,%1,%2,%3}, {%4,%5,%6,%7}, {%8,%9}, {%0,%1,%2,%3};" \
        : "+f"((d)[0]), "+f"((d)[1]), "+f"((d)[2]), "+f"((d)[3]) \
        : "r"((a)[0]), "r"((a)[1]), "r"((a)[2]), "r"((a)[3]), \
          "r"((b)[0]), "r"((b)[1]))

// CTA tile 128(M) x 128(N), templated BK. Row bytes = 2*BK + 16 pad
// (16B-aligned; stride mod 128B = 16 -> 8 ldmatrix rows hit distinct 16B
// slots -> conflict-free). 2-stage cp.async pipeline, single-buffered frags.

template<int BKT>
__device__ __forceinline__ void issue_stage(
    uint32_t sb,
    const __nv_bfloat16* __restrict__ Ah, const __nv_bfloat16* __restrict__ Al, int lda,
    const __nv_bfloat16* __restrict__ Bh, const __nv_bfloat16* __restrict__ Bl, int ldb,
    int k0, int t)
{
    constexpr int ROWB = 2*BKT + 16;
    constexpr int TILE = 128*ROWB;
    const int row = t >> 1, half = t & 1;
    const uint32_t so = (uint32_t)(row*ROWB + half*BKT);
    const size_t ga = (size_t)row*lda + k0 + half*(BKT/2);
    const size_t gb = (size_t)row*ldb + k0 + half*(BKT/2);
    #pragma unroll
    for (int i = 0; i < BKT/16; ++i){
        cp16(sb +          so + i*16, Ah + ga + i*8);
        cp16(sb +   TILE + so + i*16, Al + ga + i*8);
        cp16(sb + 2*TILE + so + i*16, Bh + gb + i*8);
        cp16(sb + 3*TILE + so + i*16, Bl + gb + i*8);
    }
}

// warp grid 2(m) x 4(n), warp tile 64x32, single-buffered fragments.
template<int BKT>
__device__ __forceinline__ void compute_stage(
    uint32_t sb, int warp_m, int warp_n, int lane, float acc[4][4][4])
{
    constexpr int ROWB = 2*BKT + 16;
    constexpr int TILE = 128*ROWB;
    constexpr int NKK  = BKT/16;
    const int arow = lane & 15;
    const int acol = (lane >> 4) * 8;
    const int brow = lane & 7;
    const int bcol = ((lane >> 3) & 1) * 8;

    #pragma unroll
    for (int kk = 0; kk < NKK; ++kk){
        uint32_t ah[4][4], al[4][4], bh[4][2], bl[4][2];
        #pragma unroll
        for (int mt = 0; mt < 4; ++mt){
            const uint32_t ao = (uint32_t)((warp_m*64 + mt*16 + arow)*ROWB + (kk*16 + acol)*2);
            LDM4(ah[mt], sb + ao);
            LDM4(al[mt], sb + TILE + ao);
        }
        #pragma unroll
        for (int nt = 0; nt < 4; ++nt){
            const uint32_t bo = (uint32_t)((warp_n*32 + nt*8 + brow)*ROWB + (kk*16 + bcol)*2);
            LDM2(bh[nt], sb + 2*TILE + bo);
            LDM2(bl[nt], sb + 3*TILE + bo);
        }
        #pragma unroll
        for (int mt = 0; mt < 4; ++mt)
            #pragma unroll
            for (int nt = 0; nt < 4; ++nt)
                MMA_BF16(acc[mt][nt], ah[mt], bh[nt]);
        #pragma unroll
        for (int mt = 0; mt < 4; ++mt)
            #pragma unroll
            for (int nt = 0; nt < 4; ++nt)
                MMA_BF16(acc[mt][nt], ah[mt], bl[nt]);
        #pragma unroll
        for (int mt = 0; mt < 4; ++mt)
            #pragma unroll
            for (int nt = 0; nt < 4; ++nt)
                MMA_BF16(acc[mt][nt], al[mt], bh[nt]);
    }
}

// GEMM core: acc = A[128,K] @ B^T[128,K], 2-stage pipeline. K/BKT >= 2.
template<int BKT>
__device__ __forceinline__ void gemm_mma(
    const __nv_bfloat16* __restrict__ Ah, const __nv_bfloat16* __restrict__ Al, int lda,
    const __nv_bfloat16* __restrict__ Bh, const __nv_bfloat16* __restrict__ Bl, int ldb,
    int K, float acc[4][4][4], char* smem)
{
    constexpr int STAGE = 4*128*(2*BKT + 16);
    const uint32_t sb = smem_u32(smem);
    const int t = threadIdx.x;
    const int lane = t & 31, wid = t >> 5;
    const int warp_m = wid & 1, warp_n = wid >> 1;

    #pragma unroll
    for (int i = 0; i < 4; ++i)
        #pragma unroll
        for (int j = 0; j < 4; ++j)
            #pragma unroll
            for (int r = 0; r < 4; ++r) acc[i][j][r] = 0.0f;

    const int nIter = K / BKT;
    issue_stage<BKT>(sb, Ah, Al, lda, Bh, Bl, ldb, 0, t);
    CP_COMMIT();

    for (int it = 0; it < nIter; ++it){
        if (it + 1 < nIter){
            issue_stage<BKT>(sb + ((it+1)&1)*STAGE, Ah, Al, lda, Bh, Bl, ldb, (it+1)*BKT, t);
            CP_COMMIT();
            CP_WAIT1();
        } else {
            CP_WAIT0();
        }
        __syncthreads();
        compute_stage<BKT>(sb + (it&1)*STAGE, warp_m, warp_n, lane, acc);
        __syncthreads();
    }
}

#define SMEM_G12 (2*4*128*(2*64+16))   /* BK=64: 147456 */
#define SMEM_G3  (2*4*128*(2*32+16))   /* BK=32:  81920 */

// ---------------------------------------------------------------------------
// prep kernel: blocks [0,256) = distance partial sums (j-halves);
//              blocks [256, 4864) = weight transpose + split.
// ---------------------------------------------------------------------------
__device__ void dist_partial_body(const float* __restrict__ xv,
                                  const float* __restrict__ xa, int q)
{
    const int dir  = q & 1;
    const int b    = (q >> 1) & 1;
    const int half = (q >> 2) & 1;
    const int i0   = (q >> 3) * 8;
    const float* self  = dir ? xa : xv;
    const float* other = dir ? xv : xa;

    const int t = threadIdx.x;
    const ull* sb_ = reinterpret_cast<const ull*>(self  + (size_t)b*NTOK*DD);
    const ull* ob_ = reinterpret_cast<const ull*>(other + (size_t)b*NTOK*DD);

    ull a[8], acc[8];
    #pragma unroll
    for (int r = 0; r < 8; ++r){
        a[r] = sb_[(size_t)(i0+r)*256 + t];
        acc[r] = 0ull;
    }
    const ull SGN = 0x8000000080000000ull;
    const ull ABS = 0x7FFFFFFF7FFFFFFFull;

    const int j0 = half * 128;
    #pragma unroll 2
    for (int j = j0; j < j0 + 128; ++j){
        const ull on = ob_[(size_t)j*256 + t] ^ SGN;
        #pragma unroll
        for (int r = 0; r < 8; ++r){
            ull d = addx2(a[r], on);
            d &= ABS;
            acc[r] = addx2(acc[r], d);
        }
    }

    __shared__ float red[8][256];
    #pragma unroll
    for (int r = 0; r < 8; ++r){
        float2 p = unpk2(acc[r]);
        red[r][t] = p.x + p.y;
    }
    __syncthreads();
    for (int s = 128; s > 0; s >>= 1){
        if (t < s){
            #pragma unroll
            for (int r = 0; r < 8; ++r) red[r][t] += red[r][t+s];
        }
        __syncthreads();
    }
    if (t < 8)
        g_dsum[(((dir*BB + b)*NTOK) + i0 + t)*2 + half] = red[t][0];
}

__device__ void transpose_body(const float* __restrict__ W1v, const float* __restrict__ W1a,
                               const float* __restrict__ Wmv, const float* __restrict__ Wma,
                               const float* __restrict__ Wout, int bid)
{
    const float* src; __nv_bfloat16 *dhi, *dlo; int R, C, ti;
    if (bid < 1024)      { src=W1v;  dhi=g_w1thi;        dlo=g_w1tlo;        R=512;  C=2048; ti=bid; }
    else if (bid < 2048) { src=W1a;  dhi=g_w1thi+HH*DD;  dlo=g_w1tlo+HH*DD;  R=512;  C=2048; ti=bid-1024; }
    else if (bid < 3072) { src=Wmv;  dhi=g_wmthi;        dlo=g_wmtlo;        R=2048; C=512;  ti=bid-2048; }
    else if (bid < 4096) { src=Wma;  dhi=g_wmthi+DD*HH;  dlo=g_wmtlo+DD*HH;  R=2048; C=512;  ti=bid-3072; }
    else                 { src=Wout; dhi=g_wothi;        dlo=g_wotlo;        R=1024; C=512;  ti=bid-4096; }

    const int TC_ = C >> 5;
    const int c0 = (ti % TC_) * 32;
    const int r0 = (ti / TC_) * 32;

    __shared__ float s[32][33];
    const int tx = threadIdx.x & 31;
    const int ty = threadIdx.x >> 5;

    #pragma unroll
    for (int i = 0; i < 4; ++i)
        s[ty + 8*i][tx] = src[(size_t)(r0 + ty + 8*i)*C + c0 + tx];
    __syncthreads();

    #pragma unroll
    for (int i = 0; i < 4; ++i){
        const int cc = ty + 8*i;
        const float v = s[tx][cc];
        __nv_bfloat16 h, l;
        split_bf16(v, h, l);
        dhi[(size_t)(c0 + cc)*R + r0 + tx] = h;
        dlo[(size_t)(c0 + cc)*R + r0 + tx] = l;
    }
}

__global__ void __launch_bounds__(256)
prep_kernel(const float* __restrict__ xv, const float* __restrict__ xa,
            const float* __restrict__ W1v, const float* __restrict__ W1a,
            const float* __restrict__ Wmv, const float* __restrict__ Wma,
            const float* __restrict__ Wout)
{
    if (blockIdx.x < 256) dist_partial_body(xv, xa, blockIdx.x);
    else                  transpose_body(W1v, W1a, Wmv, Wma, Wout, blockIdx.x - 256);
}

// ---------------------------------------------------------------------------
// weight kernel: xw = x * mean_dist -> bf16 hi/lo.  grid 128, 256 thr.
// ---------------------------------------------------------------------------
__global__ void __launch_bounds__(256)
weight_kernel(const float* __restrict__ xv, const float* __restrict__ xa)
{
    const int q  = blockIdx.x;
    const int dir = q & 1;
    const int b   = (q >> 1) & 1;
    const int i0  = (q >> 2) * 8;
    const float* self = dir ? xa : xv;
    __nv_bfloat16* ohi = g_xwhi + (size_t)dir*MM*DD;
    __nv_bfloat16* olo = g_xwlo + (size_t)dir*MM*DD;

    const int t = threadIdx.x;
    const ull* sb_ = reinterpret_cast<const ull*>(self + (size_t)b*NTOK*DD);
    const float inv = 1.0f / (float)NTOK;

    #pragma unroll
    for (int r = 0; r < 8; ++r){
        const int row = i0 + r;
        const float* ds = &g_dsum[(((dir*BB + b)*NTOK) + row)*2];
        const float s = (ds[0] + ds[1]) * inv;
        const float2 av = unpk2(sb_[(size_t)row*256 + t]);
        const float v0 = av.x * s, v1 = av.y * s;
        __nv_bfloat16 h0, l0, h1, l1;
        split_bf16(v0, h0, l0);
        split_bf16(v1, h1, l1);
        __nv_bfloat162 ph; ph.x = h0; ph.y = h1;
        __nv_bfloat162 pl; pl.x = l0; pl.y = l1;
        const size_t o = (size_t)(b*NTOK + row)*DD + 2*t;
        *reinterpret_cast<__nv_bfloat162*>(ohi + o) = ph;
        *reinterpret_cast<__nv_bfloat162*>(olo + o) = pl;
    }
}

// ---------------------------------------------------------------------------
// G1: h1 = gelu(xw @ W1 + b1) -> bf16 hi/lo.  grid (16, 4, 2), 256 thr.
// ---------------------------------------------------------------------------
__global__ void __launch_bounds__(256)
g1_mma(const float* __restrict__ b1v, const float* __restrict__ b1a)
{
    extern __shared__ char smem[];
    const int side = blockIdx.z;
    const int n0 = blockIdx.x * 128, m0 = blockIdx.y * 128;

    const __nv_bfloat16* Ah = g_xwhi  + (size_t)side*MM*DD + (size_t)m0*DD;
    const __nv_bfloat16* Al = g_xwlo  + (size_t)side*MM*DD + (size_t)m0*DD;
    const __nv_bfloat16* Bh = g_w1thi + (size_t)side*HH*DD + (size_t)n0*DD;
    const __nv_bfloat16* Bl = g_w1tlo + (size_t)side*HH*DD + (size_t)n0*DD;

    float acc[4][4][4];
    gemm_mma<64>(Ah, Al, DD, Bh, Bl, DD, DD, acc, smem);

    const float* bias = side ? b1a : b1v;
    __nv_bfloat16* Hh = g_h1hi + (size_t)side*MM*HH;
    __nv_bfloat16* Hl = g_h1lo + (size_t)side*MM*HH;

    const int lane = threadIdx.x & 31, wid = threadIdx.x >> 5;
    const int warp_m = wid & 1, warp_n = wid >> 1;

    #pragma unroll
    for (int mt = 0; mt < 4; ++mt){
        #pragma unroll
        for (int nt = 0; nt < 4; ++nt){
            const int row = m0 + warp_m*64 + mt*16 + (lane >> 2);
            const int col = n0 + warp_n*32 + nt*8  + (lane & 3)*2;
            const float bb0 = bias[col], bb1 = bias[col+1];
            #pragma unroll
            for (int h = 0; h < 2; ++h){
                const int rr = row + h*8;
                float v0 = gelu1(acc[mt][nt][2*h]   + bb0);
                float v1 = gelu1(acc[mt][nt][2*h+1] + bb1);
                __nv_bfloat16 h0, l0, h1, l1;
                split_bf16(v0, h0, l0);
                split_bf16(v1, h1, l1);
                __nv_bfloat162 ph; ph.x = h0; ph.y = h1;
                __nv_bfloat162 pl; pl.x = l0; pl.y = l1;
                *reinterpret_cast<__nv_bfloat162*>(Hh + (size_t)rr*HH + col) = ph;
                *reinterpret_cast<__nv_bfloat162*>(Hl + (size_t)rr*HH + col) = pl;
            }
        }
    }
}

// ---------------------------------------------------------------------------
// G2: p2[side][sp] = h1[:, sp*512:(sp+1)*512] @ WmT.  grid (4, 4, 8), 256 thr.
// ---------------------------------------------------------------------------
__global__ void __launch_bounds__(256)
g2_mma()
{
    extern __shared__ char smem[];
    const int side = blockIdx.z & 1;
    const int sp   = blockIdx.z >> 1;
    const int n0 = blockIdx.x * 128, m0 = blockIdx.y * 128;
    const int ko = sp * 512;

    const __nv_bfloat16* Ah = g_h1hi  + (size_t)side*MM*HH + (size_t)m0*HH + ko;
    const __nv_bfloat16* Al = g_h1lo  + (size_t)side*MM*HH + (size_t)m0*HH + ko;
    const __nv_bfloat16* Bh = g_wmthi + (size_t)side*DD*HH + (size_t)n0*HH + ko;
    const __nv_bfloat16* Bl = g_wmtlo + (size_t)side*DD*HH + (size_t)n0*HH + ko;

    float acc[4][4][4];
    gemm_mma<64>(Ah, Al, HH, Bh, Bl, HH, 512, acc, smem);

    float* C = g_p2 + (size_t)(side*4 + sp)*MM*DD;
    const int lane = threadIdx.x & 31, wid = threadIdx.x >> 5;
    const int warp_m = wid & 1, warp_n = wid >> 1;

    #pragma unroll
    for (int mt = 0; mt < 4; ++mt){
        #pragma unroll
        for (int nt = 0; nt < 4; ++nt){
            const int row = m0 + warp_m*64 + mt*16 + (lane >> 2);
            const int col = n0 + warp_n*32 + nt*8  + (lane & 3)*2;
            #pragma unroll
            for (int h = 0; h < 2; ++h){
                *reinterpret_cast<float2*>(C + (size_t)(row + h*8)*DD + col) =
                    make_float2(acc[mt][nt][2*h], acc[mt][nt][2*h+1]);
            }
        }
    }
}

// ---------------------------------------------------------------------------
// Reduce G2 partials + bias -> comb bf16 hi/lo.  2 positions/thread.
// ---------------------------------------------------------------------------
__global__ void __launch_bounds__(256)
reduce_g2(const float* __restrict__ bmv, const float* __restrict__ bma)
{
    const int idx = blockIdx.x * 256 + threadIdx.x;   // [0, 65536)
    #pragma unroll
    for (int p = 0; p < 2; ++p){
        const int q = idx + p*65536;
        const int n = (q & 255) * 4;
        const int m = q >> 8;
        const int side = n >> 9;
        const int c = n & 511;

        const float* P = g_p2 + (size_t)side*4*MM*DD + (size_t)m*DD + c;
        float4 v0 = *reinterpret_cast<const float4*>(P);
        float4 v1 = *reinterpret_cast<const float4*>(P + MM*DD);
        float4 v2 = *reinterpret_cast<const float4*>(P + 2*MM*DD);
        float4 v3 = *reinterpret_cast<const float4*>(P + 3*MM*DD);
        const float* bias = side ? bma : bmv;
        float4 bb = *reinterpret_cast<const float4*>(bias + c);

        float v[4];
        v[0] = v0.x + v1.x + v2.x + v3.x + bb.x;
        v[1] = v0.y + v1.y + v2.y + v3.y + bb.y;
        v[2] = v0.z + v1.z + v2.z + v3.z + bb.z;
        v[3] = v0.w + v1.w + v2.w + v3.w + bb.w;

        const size_t o = (size_t)m*(2*DD) + n;
        #pragma unroll
        for (int i = 0; i < 4; i += 2){
            __nv_bfloat16 h0, l0, h1, l1;
            split_bf16(v[i],   h0, l0);
            split_bf16(v[i+1], h1, l1);
            __nv_bfloat162 ph; ph.x = h0; ph.y = h1;
            __nv_bfloat162 pl; pl.x = l0; pl.y = l1;
            *reinterpret_cast<__nv_bfloat162*>(g_combhi + o + i) = ph;
            *reinterpret_cast<__nv_bfloat162*>(g_comblo + o + i) = pl;
        }
    }
}

// ---------------------------------------------------------------------------
// G3: p3[sp] = comb[:, sp*128:(sp+1)*128] @ WoutT.  grid (4, 4, 8), 256 thr.
// ---------------------------------------------------------------------------
__global__ void __launch_bounds__(256)
g3_mma()
{
    extern __shared__ char smem[];
    const int sp = blockIdx.z;
    const int n0 = blockIdx.x * 128, m0 = blockIdx.y * 128;
    const int ko = sp * 128;

    const __nv_bfloat16* Ah = g_combhi + (size_t)m0*(2*DD) + ko;
    const __nv_bfloat16* Al = g_comblo + (size_t)m0*(2*DD) + ko;
    const __nv_bfloat16* Bh = g_wothi  + (size_t)n0*(2*DD) + ko;
    const __nv_bfloat16* Bl = g_wotlo  + (size_t)n0*(2*DD) + ko;

    float acc[4][4][4];
    gemm_mma<32>(Ah, Al, 2*DD, Bh, Bl, 2*DD, 128, acc, smem);

    float* C = g_p3 + (size_t)sp*MM*DD;
    const int lane = threadIdx.x & 31, wid = threadIdx.x >> 5;
    const int warp_m = wid & 1, warp_n = wid >> 1;

    #pragma unroll
    for (int mt = 0; mt < 4; ++mt){
        #pragma unroll
        for (int nt = 0; nt < 4; ++nt){
            const int row = m0 + warp_m*64 + mt*16 + (lane >> 2);
            const int col = n0 + warp_n*32 + nt*8  + (lane & 3)*2;
            #pragma unroll
            for (int h = 0; h < 2; ++h){
                *reinterpret_cast<float2*>(C + (size_t)(row + h*8)*DD + col) =
                    make_float2(acc[mt][nt][2*h], acc[mt][nt][2*h+1]);
            }
        }
    }
}

// ---------------------------------------------------------------------------
// Reduce G3 partials + bout -> out fp32.  2 positions/thread.
// ---------------------------------------------------------------------------
__global__ void __launch_bounds__(256)
reduce_g3(float* __restrict__ out, const float* __restrict__ bout)
{
    const int idx = blockIdx.x * 256 + threadIdx.x;   // [0, 32768)
    #pragma unroll
    for (int p = 0; p < 2; ++p){
        const int q = idx + p*32768;
        const int n = (q & 127) * 4;
        const int m = q >> 7;
        const size_t o = (size_t)m*DD + n;

        float4 r = *reinterpret_cast<const float4*>(bout + n);
        #pragma unroll
        for (int sp = 0; sp < 8; ++sp){
            float4 v = *reinterpret_cast<const float4*>(g_p3 + (size_t)sp*MM*DD + o);
            r.x += v.x; r.y += v.y; r.z += v.z; r.w += v.w;
        }
        *reinterpret_cast<float4*>(out + o) = r;
    }
}

// ---------------------------------------------------------------------------
extern "C" void kernel_launch(void* const* d_in, const int* in_sizes, int n_in,
                              void* d_out, int out_size)
{
    (void)in_sizes; (void)n_in; (void)out_size;

    const float* x_v  = (const float*)d_in[0];
    const float* x_a  = (const float*)d_in[1];
    const float* W1v  = (const float*)d_in[2];
    const float* b1v  = (const float*)d_in[3];
    const float* W1a  = (const float*)d_in[4];
    const float* b1a  = (const float*)d_in[5];
    const float* Wmv  = (const float*)d_in[6];
    const float* bmv  = (const float*)d_in[7];
    const float* Wma  = (const float*)d_in[8];
    const float* bma  = (const float*)d_in[9];
    const float* Wout = (const float*)d_in[10];
    const float* bout = (const float*)d_in[11];
    float* out = (float*)d_out;

    cudaFuncSetAttribute(g1_mma, cudaFuncAttributeMaxDynamicSharedMemorySize, SMEM_G12);
    cudaFuncSetAttribute(g2_mma, cudaFuncAttributeMaxDynamicSharedMemorySize, SMEM_G12);
    cudaFuncSetAttribute(g3_mma, cudaFuncAttributeMaxDynamicSharedMemorySize, SMEM_G3);

    // 1) prep: dist partial sums [0,256) + weight transpose/split [256,4864)
    prep_kernel<<<4864, 256>>>(x_v, x_a, W1v, W1a, Wmv, Wma, Wout);

    // 2) xw = x * mean_dist -> bf16 split
    weight_kernel<<<128, 256>>>(x_v, x_a);

    // 3) G1: h1 = gelu(xw @ W1 + b1) -> bf16 split   (128 CTAs, BK=64)
    g1_mma<<<dim3(HH/128, MM/128, 2), 256, SMEM_G12>>>(b1v, b1a);

    // 4) G2: split-K=4 partials per side             (128 CTAs, BK=64)
    g2_mma<<<dim3(DD/128, MM/128, 8), 256, SMEM_G12>>>();

    // 5) comb = sum partials + bias -> bf16 split
    reduce_g2<<<256, 256>>>(bmv, bma);

    // 6) G3: split-K=8 partials                      (128 CTAs, BK=32)
    g3_mma<<<dim3(DD/128, MM/128, 8), 256, SMEM_G3>>>();

    // 7) out = sum partials + bout
    reduce_g3<<<128, 256>>>(out, bout);
}